// round 3
// baseline (speedup 1.0000x reference)
#include <cuda_runtime.h>

#define VOL (1<<20)   // 32^4

// Wilson Dslash, DeGrand-Rossi basis, spin-projection (half-spinor) form.
// psi: [V][4][3] re/im separate. U: [V][4][3][3] re/im separate.
// out: res_re at [0, V*12), res_im at [V*12, 2*V*12).
//
// U matrices are staged through shared memory with cooperative slice-gather
// loads (runs of 36B instead of 32 scattered lanes), then read back with a
// stride-9 (coprime 32 -> conflict-free) LDS pattern.

template<int MU, int FWD>
__device__ __forceinline__ void hop_smem(int nbr,
                                         const float* __restrict__ pr, const float* __restrict__ pi,
                                         const float* su_r, const float* su_i,
                                         float rr[12], float ri[12])
{
    // ---- load neighbor spinor (12 complex), vectorized float4 ----
    float vr[12], vi[12];
    {
        const float4* p4 = reinterpret_cast<const float4*>(pr + (size_t)nbr * 12);
        float4 a = __ldg(p4 + 0), b = __ldg(p4 + 1), c = __ldg(p4 + 2);
        vr[0]=a.x; vr[1]=a.y; vr[2]=a.z; vr[3]=a.w;
        vr[4]=b.x; vr[5]=b.y; vr[6]=b.z; vr[7]=b.w;
        vr[8]=c.x; vr[9]=c.y; vr[10]=c.z; vr[11]=c.w;
    }
    {
        const float4* p4 = reinterpret_cast<const float4*>(pi + (size_t)nbr * 12);
        float4 a = __ldg(p4 + 0), b = __ldg(p4 + 1), c = __ldg(p4 + 2);
        vi[0]=a.x; vi[1]=a.y; vi[2]=a.z; vi[3]=a.w;
        vi[4]=b.x; vi[5]=b.y; vi[6]=b.z; vi[7]=b.w;
        vi[8]=c.x; vi[9]=c.y; vi[10]=c.z; vi[11]=c.w;
    }

    // ---- spin projection: h0 (hr[0..2]), h1 (hr[3..5]) ----
    float hr[6], hi[6];
#pragma unroll
    for (int c = 0; c < 3; ++c) {
        if (FWD) { // Pm = 1 - gamma_mu
            if (MU == 0) {
                hr[c]   = vr[c]   + vi[9+c]; hi[c]   = vi[c]   - vr[9+c];
                hr[3+c] = vr[3+c] + vi[6+c]; hi[3+c] = vi[3+c] - vr[6+c];
            } else if (MU == 1) {
                hr[c]   = vr[c]   + vr[9+c]; hi[c]   = vi[c]   + vi[9+c];
                hr[3+c] = vr[3+c] - vr[6+c]; hi[3+c] = vi[3+c] - vi[6+c];
            } else if (MU == 2) {
                hr[c]   = vr[c]   + vi[6+c]; hi[c]   = vi[c]   - vr[6+c];
                hr[3+c] = vr[3+c] - vi[9+c]; hi[3+c] = vi[3+c] + vr[9+c];
            } else {
                hr[c]   = vr[c]   - vr[6+c]; hi[c]   = vi[c]   - vi[6+c];
                hr[3+c] = vr[3+c] - vr[9+c]; hi[3+c] = vi[3+c] - vi[9+c];
            }
        } else { // Pp = 1 + gamma_mu
            if (MU == 0) {
                hr[c]   = vr[c]   - vi[9+c]; hi[c]   = vi[c]   + vr[9+c];
                hr[3+c] = vr[3+c] - vi[6+c]; hi[3+c] = vi[3+c] + vr[6+c];
            } else if (MU == 1) {
                hr[c]   = vr[c]   - vr[9+c]; hi[c]   = vi[c]   - vi[9+c];
                hr[3+c] = vr[3+c] + vr[6+c]; hi[3+c] = vi[3+c] + vi[6+c];
            } else if (MU == 2) {
                hr[c]   = vr[c]   - vi[6+c]; hi[c]   = vi[c]   + vr[6+c];
                hr[3+c] = vr[3+c] + vi[9+c]; hi[3+c] = vi[3+c] - vr[9+c];
            } else {
                hr[c]   = vr[c]   + vr[6+c]; hi[c]   = vi[c]   + vi[6+c];
                hr[3+c] = vr[3+c] + vr[9+c]; hi[3+c] = vi[3+c] + vi[9+c];
            }
        }
    }

    // ---- U matrix from shared memory (stride-9 per site: conflict-free) ----
    float u_r[9], u_i[9];
#pragma unroll
    for (int k = 0; k < 9; ++k) { u_r[k] = su_r[k]; u_i[k] = su_i[k]; }

    // ---- color multiply: a = U h (fwd) or U^dag h (bwd) ----
    float ar[6] = {0,0,0,0,0,0}, ai[6] = {0,0,0,0,0,0};
#pragma unroll
    for (int i = 0; i < 3; ++i) {
#pragma unroll
        for (int j = 0; j < 3; ++j) {
            float urr = FWD ? u_r[i*3 + j] :  u_r[j*3 + i];
            float uii = FWD ? u_i[i*3 + j] : -u_i[j*3 + i];
            ar[i]   += urr*hr[j]   - uii*hi[j];
            ai[i]   += urr*hi[j]   + uii*hr[j];
            ar[3+i] += urr*hr[3+j] - uii*hi[3+j];
            ai[3+i] += urr*hi[3+j] + uii*hr[3+j];
        }
    }

    // ---- reconstruct ----
#pragma unroll
    for (int c = 0; c < 3; ++c) {
        rr[c]   += ar[c];   ri[c]   += ai[c];
        rr[3+c] += ar[3+c]; ri[3+c] += ai[3+c];
        if (FWD) {
            if (MU == 0) {
                rr[6+c] -= ai[3+c]; ri[6+c] += ar[3+c];
                rr[9+c] -= ai[c];   ri[9+c] += ar[c];
            } else if (MU == 1) {
                rr[6+c] -= ar[3+c]; ri[6+c] -= ai[3+c];
                rr[9+c] += ar[c];   ri[9+c] += ai[c];
            } else if (MU == 2) {
                rr[6+c] -= ai[c];   ri[6+c] += ar[c];
                rr[9+c] += ai[3+c]; ri[9+c] -= ar[3+c];
            } else {
                rr[6+c] -= ar[c];   ri[6+c] -= ai[c];
                rr[9+c] -= ar[3+c]; ri[9+c] -= ai[3+c];
            }
        } else {
            if (MU == 0) {
                rr[6+c] += ai[3+c]; ri[6+c] -= ar[3+c];
                rr[9+c] += ai[c];   ri[9+c] -= ar[c];
            } else if (MU == 1) {
                rr[6+c] += ar[3+c]; ri[6+c] += ai[3+c];
                rr[9+c] -= ar[c];   ri[9+c] -= ai[c];
            } else if (MU == 2) {
                rr[6+c] += ai[c];   ri[6+c] -= ar[c];
                rr[9+c] -= ai[3+c]; ri[9+c] += ar[3+c];
            } else {
                rr[6+c] += ar[c];   ri[6+c] += ai[c];
                rr[9+c] += ar[3+c]; ri[9+c] += ai[3+c];
            }
        }
    }
}

template<int MU>
__device__ __forceinline__ void do_mu(int tid, int base, int fw, int bw,
                                      const float* __restrict__ psi_re, const float* __restrict__ psi_im,
                                      const float* __restrict__ U_re,  const float* __restrict__ U_im,
                                      float* sFr, float* sFi, float* sBr, float* sBi,
                                      float rr[12], float ri[12])
{
    const int S  = (MU==0) ? 32768 : (MU==1) ? 1024 : (MU==2) ? 32 : 1;
    const int SH = (MU==0) ? 15    : (MU==1) ? 10   : (MU==2) ? 5  : 0;

    __syncthreads();   // previous mu's smem reads complete before overwrite

    // cooperative slice-gather: 2304 elements per buffer, 9 per thread.
    // g -> (site s = g/9, element j = g%9); addresses are runs of 9 floats.
#pragma unroll
    for (int r = 0; r < 9; ++r) {
        int g = tid + 256 * r;
        int s = g / 9;
        int j = g - s * 9;
        int fs = base + s;
        size_t fa = (size_t)fs * 36 + MU * 9 + j;
        sFr[g] = __ldg(U_re + fa);
        sFi[g] = __ldg(U_im + fa);
        int xm = (fs >> SH) & 31;
        int bs = xm ? (fs - S) : (fs + 31 * S);
        size_t ba = (size_t)bs * 36 + MU * 9 + j;
        sBr[g] = __ldg(U_re + ba);
        sBi[g] = __ldg(U_im + ba);
    }
    __syncthreads();

    hop_smem<MU, 1>(fw, psi_re, psi_im, sFr + tid * 9, sFi + tid * 9, rr, ri);
    hop_smem<MU, 0>(bw, psi_re, psi_im, sBr + tid * 9, sBi + tid * 9, rr, ri);
}

__global__ void __launch_bounds__(256, 3)
dslash_kernel(const float* __restrict__ psi_re, const float* __restrict__ psi_im,
              const float* __restrict__ U_re,  const float* __restrict__ U_im,
              float* __restrict__ out_re, float* __restrict__ out_im)
{
    __shared__ float sFr[2304], sFi[2304], sBr[2304], sBi[2304];

    int tid  = threadIdx.x;
    int base = blockIdx.x * 256;
    int site = base + tid;

    int x3 =  site        & 31;
    int x2 = (site >> 5)  & 31;
    int x1 = (site >> 10) & 31;
    int x0 = (site >> 15) & 31;

    const int S0 = 32768, S1 = 1024, S2 = 32, S3 = 1;

    int fw0 = (x0 < 31) ? site + S0 : site - 31*S0;
    int bw0 = (x0 > 0)  ? site - S0 : site + 31*S0;
    int fw1 = (x1 < 31) ? site + S1 : site - 31*S1;
    int bw1 = (x1 > 0)  ? site - S1 : site + 31*S1;
    int fw2 = (x2 < 31) ? site + S2 : site - 31*S2;
    int bw2 = (x2 > 0)  ? site - S2 : site + 31*S2;
    int fw3 = (x3 < 31) ? site + S3 : site - 31*S3;
    int bw3 = (x3 > 0)  ? site - S3 : site + 31*S3;

    float rr[12], ri[12];
#pragma unroll
    for (int k = 0; k < 12; ++k) { rr[k] = 0.f; ri[k] = 0.f; }

    do_mu<0>(tid, base, fw0, bw0, psi_re, psi_im, U_re, U_im, sFr, sFi, sBr, sBi, rr, ri);
    do_mu<1>(tid, base, fw1, bw1, psi_re, psi_im, U_re, U_im, sFr, sFi, sBr, sBi, rr, ri);
    do_mu<2>(tid, base, fw2, bw2, psi_re, psi_im, U_re, U_im, sFr, sFi, sBr, sBi, rr, ri);
    do_mu<3>(tid, base, fw3, bw3, psi_re, psi_im, U_re, U_im, sFr, sFi, sBr, sBi, rr, ri);

    // ---- store: res = -0.5 * accum ----
    float4* o4r = reinterpret_cast<float4*>(out_re + (size_t)site * 12);
    float4* o4i = reinterpret_cast<float4*>(out_im + (size_t)site * 12);
    float4 t;
    t.x = -0.5f*rr[0]; t.y = -0.5f*rr[1]; t.z = -0.5f*rr[2];  t.w = -0.5f*rr[3];  o4r[0] = t;
    t.x = -0.5f*rr[4]; t.y = -0.5f*rr[5]; t.z = -0.5f*rr[6];  t.w = -0.5f*rr[7];  o4r[1] = t;
    t.x = -0.5f*rr[8]; t.y = -0.5f*rr[9]; t.z = -0.5f*rr[10]; t.w = -0.5f*rr[11]; o4r[2] = t;
    t.x = -0.5f*ri[0]; t.y = -0.5f*ri[1]; t.z = -0.5f*ri[2];  t.w = -0.5f*ri[3];  o4i[0] = t;
    t.x = -0.5f*ri[4]; t.y = -0.5f*ri[5]; t.z = -0.5f*ri[6];  t.w = -0.5f*ri[7];  o4i[1] = t;
    t.x = -0.5f*ri[8]; t.y = -0.5f*ri[9]; t.z = -0.5f*ri[10]; t.w = -0.5f*ri[11]; o4i[2] = t;
}

extern "C" void kernel_launch(void* const* d_in, const int* in_sizes, int n_in,
                              void* d_out, int out_size)
{
    const float* psi_re = (const float*)d_in[0];
    const float* psi_im = (const float*)d_in[1];
    const float* U_re   = (const float*)d_in[2];
    const float* U_im   = (const float*)d_in[3];
    // d_in[4..7] are the fixed DeGrand-Rossi projectors; algebra is hardcoded.

    float* out_re = (float*)d_out;
    float* out_im = out_re + (size_t)VOL * 12;

    dslash_kernel<<<VOL / 256, 256>>>(psi_re, psi_im, U_re, U_im, out_re, out_im);
}

// round 4
// speedup vs baseline: 1.8843x; 1.8843x over previous
#include <cuda_runtime.h>

#define VOL (1<<20)   // 32^4

// Wilson Dslash, DeGrand-Rossi basis, spin-projection form.
// psi: [V][4][3] re/im separate. U: [V][4][3][3] re/im separate.
// out: res_re at [0, V*12), res_im at [V*12, 2*V*12).
//
// U strategy (whole-site granularity -> compulsory DRAM):
//  - own site U loaded as 18x LDG.128, used for all 4 forward hops
//  - mu=2,3 backward-neighbor slices shared through smem (in-block)
//  - mu=0,1 backward slices (and x2-boundary mu=2) read scalar from global

template<int MU, int FWD>
__device__ __forceinline__ void hop(int nbr,
                                    const float* __restrict__ pr, const float* __restrict__ pi,
                                    const float* u_r, const float* u_i,
                                    float rr[12], float ri[12])
{
    // ---- neighbor spinor, vectorized float4 ----
    float vr[12], vi[12];
    {
        const float4* p4 = reinterpret_cast<const float4*>(pr + (size_t)nbr * 12);
        float4 a = __ldg(p4 + 0), b = __ldg(p4 + 1), c = __ldg(p4 + 2);
        vr[0]=a.x; vr[1]=a.y; vr[2]=a.z; vr[3]=a.w;
        vr[4]=b.x; vr[5]=b.y; vr[6]=b.z; vr[7]=b.w;
        vr[8]=c.x; vr[9]=c.y; vr[10]=c.z; vr[11]=c.w;
    }
    {
        const float4* p4 = reinterpret_cast<const float4*>(pi + (size_t)nbr * 12);
        float4 a = __ldg(p4 + 0), b = __ldg(p4 + 1), c = __ldg(p4 + 2);
        vi[0]=a.x; vi[1]=a.y; vi[2]=a.z; vi[3]=a.w;
        vi[4]=b.x; vi[5]=b.y; vi[6]=b.z; vi[7]=b.w;
        vi[8]=c.x; vi[9]=c.y; vi[10]=c.z; vi[11]=c.w;
    }

    // ---- spin projection ----
    float hr[6], hi[6];
#pragma unroll
    for (int c = 0; c < 3; ++c) {
        if (FWD) { // Pm = 1 - gamma_mu
            if (MU == 0) {
                hr[c]   = vr[c]   + vi[9+c]; hi[c]   = vi[c]   - vr[9+c];
                hr[3+c] = vr[3+c] + vi[6+c]; hi[3+c] = vi[3+c] - vr[6+c];
            } else if (MU == 1) {
                hr[c]   = vr[c]   + vr[9+c]; hi[c]   = vi[c]   + vi[9+c];
                hr[3+c] = vr[3+c] - vr[6+c]; hi[3+c] = vi[3+c] - vi[6+c];
            } else if (MU == 2) {
                hr[c]   = vr[c]   + vi[6+c]; hi[c]   = vi[c]   - vr[6+c];
                hr[3+c] = vr[3+c] - vi[9+c]; hi[3+c] = vi[3+c] + vr[9+c];
            } else {
                hr[c]   = vr[c]   - vr[6+c]; hi[c]   = vi[c]   - vi[6+c];
                hr[3+c] = vr[3+c] - vr[9+c]; hi[3+c] = vi[3+c] - vi[9+c];
            }
        } else { // Pp = 1 + gamma_mu
            if (MU == 0) {
                hr[c]   = vr[c]   - vi[9+c]; hi[c]   = vi[c]   + vr[9+c];
                hr[3+c] = vr[3+c] - vi[6+c]; hi[3+c] = vi[3+c] + vr[6+c];
            } else if (MU == 1) {
                hr[c]   = vr[c]   - vr[9+c]; hi[c]   = vi[c]   - vi[9+c];
                hr[3+c] = vr[3+c] + vr[6+c]; hi[3+c] = vi[3+c] + vi[6+c];
            } else if (MU == 2) {
                hr[c]   = vr[c]   - vi[6+c]; hi[c]   = vi[c]   + vr[6+c];
                hr[3+c] = vr[3+c] + vi[9+c]; hi[3+c] = vi[3+c] - vr[9+c];
            } else {
                hr[c]   = vr[c]   + vr[6+c]; hi[c]   = vi[c]   + vi[6+c];
                hr[3+c] = vr[3+c] + vr[9+c]; hi[3+c] = vi[3+c] + vi[9+c];
            }
        }
    }

    // ---- color multiply: a = U h (fwd) or U^dag h (bwd), const-indexed ----
    float ar[6] = {0,0,0,0,0,0}, ai[6] = {0,0,0,0,0,0};
#pragma unroll
    for (int i = 0; i < 3; ++i) {
#pragma unroll
        for (int j = 0; j < 3; ++j) {
            float urr = FWD ? u_r[i*3 + j] :  u_r[j*3 + i];
            float uii = FWD ? u_i[i*3 + j] : -u_i[j*3 + i];
            ar[i]   += urr*hr[j]   - uii*hi[j];
            ai[i]   += urr*hi[j]   + uii*hr[j];
            ar[3+i] += urr*hr[3+j] - uii*hi[3+j];
            ai[3+i] += urr*hi[3+j] + uii*hr[3+j];
        }
    }

    // ---- reconstruct ----
#pragma unroll
    for (int c = 0; c < 3; ++c) {
        rr[c]   += ar[c];   ri[c]   += ai[c];
        rr[3+c] += ar[3+c]; ri[3+c] += ai[3+c];
        if (FWD) {
            if (MU == 0) {
                rr[6+c] -= ai[3+c]; ri[6+c] += ar[3+c];
                rr[9+c] -= ai[c];   ri[9+c] += ar[c];
            } else if (MU == 1) {
                rr[6+c] -= ar[3+c]; ri[6+c] -= ai[3+c];
                rr[9+c] += ar[c];   ri[9+c] += ai[c];
            } else if (MU == 2) {
                rr[6+c] -= ai[c];   ri[6+c] += ar[c];
                rr[9+c] += ai[3+c]; ri[9+c] -= ar[3+c];
            } else {
                rr[6+c] -= ar[c];   ri[6+c] -= ai[c];
                rr[9+c] -= ar[3+c]; ri[9+c] -= ai[3+c];
            }
        } else {
            if (MU == 0) {
                rr[6+c] += ai[3+c]; ri[6+c] -= ar[3+c];
                rr[9+c] += ai[c];   ri[9+c] -= ar[c];
            } else if (MU == 1) {
                rr[6+c] += ar[3+c]; ri[6+c] += ai[3+c];
                rr[9+c] -= ar[c];   ri[9+c] -= ai[c];
            } else if (MU == 2) {
                rr[6+c] += ai[c];   ri[6+c] -= ar[c];
                rr[9+c] -= ai[3+c]; ri[9+c] += ar[3+c];
            } else {
                rr[6+c] += ar[c];   ri[6+c] += ai[c];
                rr[9+c] += ar[3+c]; ri[9+c] += ai[3+c];
            }
        }
    }
}

__global__ void __launch_bounds__(256, 3)
dslash_kernel(const float* __restrict__ psi_re, const float* __restrict__ psi_im,
              const float* __restrict__ U_re,  const float* __restrict__ U_im,
              float* __restrict__ out_re, float* __restrict__ out_im)
{
    // mu=2 / mu=3 U slices, transposed [element][site] for conflict-free STS/LDS
    __shared__ float s2r[9][256], s2i[9][256], s3r[9][256], s3i[9][256];

    int tid  = threadIdx.x;
    int base = blockIdx.x * 256;
    int site = base + tid;

    int x3 =  site        & 31;
    int x2 = (site >> 5)  & 31;
    int x1 = (site >> 10) & 31;
    int x0 = (site >> 15) & 31;

    const int S0 = 32768, S1 = 1024, S2 = 32, S3 = 1;

    int fw0 = (x0 < 31) ? site + S0 : site - 31*S0;
    int bw0 = (x0 > 0)  ? site - S0 : site + 31*S0;
    int fw1 = (x1 < 31) ? site + S1 : site - 31*S1;
    int bw1 = (x1 > 0)  ? site - S1 : site + 31*S1;
    int fw2 = (x2 < 31) ? site + S2 : site - 31*S2;
    int bw2 = (x2 > 0)  ? site - S2 : site + 31*S2;
    int fw3 = (x3 < 31) ? site + S3 : site - 31*S3;
    int bw3 = (x3 > 0)  ? site - S3 : site + 31*S3;

    // ---- own-site U: 36 floats re + 36 im, vectorized LDG.128 ----
    float ur[36], ui[36];
    {
        const float4* r4 = reinterpret_cast<const float4*>(U_re + (size_t)site * 36);
        const float4* i4 = reinterpret_cast<const float4*>(U_im + (size_t)site * 36);
#pragma unroll
        for (int k = 0; k < 9; ++k) {
            reinterpret_cast<float4*>(ur)[k] = __ldg(r4 + k);
            reinterpret_cast<float4*>(ui)[k] = __ldg(i4 + k);
        }
    }

    // ---- publish mu=2 / mu=3 slices for in-block backward neighbors ----
#pragma unroll
    for (int j = 0; j < 9; ++j) {
        s2r[j][tid] = ur[18 + j];
        s2i[j][tid] = ui[18 + j];
        s3r[j][tid] = ur[27 + j];
        s3i[j][tid] = ui[27 + j];
    }

    float rr[12], ri[12];
#pragma unroll
    for (int k = 0; k < 12; ++k) { rr[k] = 0.f; ri[k] = 0.f; }

    // ---- forward hops: own-site U from registers ----
    hop<0,1>(fw0, psi_re, psi_im, ur +  0, ui +  0, rr, ri);
    hop<1,1>(fw1, psi_re, psi_im, ur +  9, ui +  9, rr, ri);
    hop<2,1>(fw2, psi_re, psi_im, ur + 18, ui + 18, rr, ri);
    hop<3,1>(fw3, psi_re, psi_im, ur + 27, ui + 27, rr, ri);

    __syncthreads();   // slices visible

    // ---- backward mu=3: always in-block (block holds full x3 rows) ----
    {
        int ntid = (tid & 31) ? tid - 1 : tid + 31;
        float br[9], bi[9];
#pragma unroll
        for (int j = 0; j < 9; ++j) { br[j] = s3r[j][ntid]; bi[j] = s3i[j][ntid]; }
        hop<3,0>(bw3, psi_re, psi_im, br, bi, rr, ri);
    }

    // ---- backward mu=2: in-block unless local x2 == 0 ----
    {
        float br[9], bi[9];
        if ((tid >> 5) != 0) {
            int ntid = tid - 32;
#pragma unroll
            for (int j = 0; j < 9; ++j) { br[j] = s2r[j][ntid]; bi[j] = s2i[j][ntid]; }
        } else {
            size_t ub = (size_t)bw2 * 36 + 18;
#pragma unroll
            for (int j = 0; j < 9; ++j) { br[j] = __ldg(U_re + ub + j); bi[j] = __ldg(U_im + ub + j); }
        }
        hop<2,0>(bw2, psi_re, psi_im, br, bi, rr, ri);
    }

    // ---- backward mu=1: global slice ----
    {
        size_t ub = (size_t)bw1 * 36 + 9;
        float br[9], bi[9];
#pragma unroll
        for (int j = 0; j < 9; ++j) { br[j] = __ldg(U_re + ub + j); bi[j] = __ldg(U_im + ub + j); }
        hop<1,0>(bw1, psi_re, psi_im, br, bi, rr, ri);
    }

    // ---- backward mu=0: global slice ----
    {
        size_t ub = (size_t)bw0 * 36;
        float br[9], bi[9];
#pragma unroll
        for (int j = 0; j < 9; ++j) { br[j] = __ldg(U_re + ub + j); bi[j] = __ldg(U_im + ub + j); }
        hop<0,0>(bw0, psi_re, psi_im, br, bi, rr, ri);
    }

    // ---- store: res = -0.5 * accum ----
    float4* o4r = reinterpret_cast<float4*>(out_re + (size_t)site * 12);
    float4* o4i = reinterpret_cast<float4*>(out_im + (size_t)site * 12);
    float4 t;
    t.x = -0.5f*rr[0]; t.y = -0.5f*rr[1]; t.z = -0.5f*rr[2];  t.w = -0.5f*rr[3];  o4r[0] = t;
    t.x = -0.5f*rr[4]; t.y = -0.5f*rr[5]; t.z = -0.5f*rr[6];  t.w = -0.5f*rr[7];  o4r[1] = t;
    t.x = -0.5f*rr[8]; t.y = -0.5f*rr[9]; t.z = -0.5f*rr[10]; t.w = -0.5f*rr[11]; o4r[2] = t;
    t.x = -0.5f*ri[0]; t.y = -0.5f*ri[1]; t.z = -0.5f*ri[2];  t.w = -0.5f*ri[3];  o4i[0] = t;
    t.x = -0.5f*ri[4]; t.y = -0.5f*ri[5]; t.z = -0.5f*ri[6];  t.w = -0.5f*ri[7];  o4i[1] = t;
    t.x = -0.5f*ri[8]; t.y = -0.5f*ri[9]; t.z = -0.5f*ri[10]; t.w = -0.5f*ri[11]; o4i[2] = t;
}

extern "C" void kernel_launch(void* const* d_in, const int* in_sizes, int n_in,
                              void* d_out, int out_size)
{
    const float* psi_re = (const float*)d_in[0];
    const float* psi_im = (const float*)d_in[1];
    const float* U_re   = (const float*)d_in[2];
    const float* U_im   = (const float*)d_in[3];
    // d_in[4..7] are the fixed DeGrand-Rossi projectors; algebra is hardcoded.

    float* out_re = (float*)d_out;
    float* out_im = out_re + (size_t)VOL * 12;

    dslash_kernel<<<VOL / 256, 256>>>(psi_re, psi_im, U_re, U_im, out_re, out_im);
}

// round 6
// speedup vs baseline: 2.0393x; 1.0823x over previous
#include <cuda_runtime.h>

#define VOL (1<<20)   // 32^4

// Wilson Dslash, DeGrand-Rossi basis, spin-projection form.
// psi: [V][4][3] re/im separate. U: [V][4][3][3] re/im separate.
// out: res_re at [0, V*12), res_im at [V*12, 2*V*12).
//
// U strategy (whole-site granularity -> compulsory DRAM):
//  - own site U loaded as 18x LDG.128, used for all 4 forward hops
//  - mu=2,3 backward-neighbor slices shared through smem (in-block)
//  - mu=0,1 backward slices (and x2-boundary mu=2) read via ALIGNED VECTOR
//    loads covering the 9-float slice (3 requests instead of 18 scalars)

template<int MU, int FWD>
__device__ __forceinline__ void hop(int nbr,
                                    const float* __restrict__ pr, const float* __restrict__ pi,
                                    const float* u_r, const float* u_i,
                                    float rr[12], float ri[12])
{
    // ---- neighbor spinor, vectorized float4 ----
    float vr[12], vi[12];
    {
        const float4* p4 = reinterpret_cast<const float4*>(pr + (size_t)nbr * 12);
        float4 a = __ldg(p4 + 0), b = __ldg(p4 + 1), c = __ldg(p4 + 2);
        vr[0]=a.x; vr[1]=a.y; vr[2]=a.z; vr[3]=a.w;
        vr[4]=b.x; vr[5]=b.y; vr[6]=b.z; vr[7]=b.w;
        vr[8]=c.x; vr[9]=c.y; vr[10]=c.z; vr[11]=c.w;
    }
    {
        const float4* p4 = reinterpret_cast<const float4*>(pi + (size_t)nbr * 12);
        float4 a = __ldg(p4 + 0), b = __ldg(p4 + 1), c = __ldg(p4 + 2);
        vi[0]=a.x; vi[1]=a.y; vi[2]=a.z; vi[3]=a.w;
        vi[4]=b.x; vi[5]=b.y; vi[6]=b.z; vi[7]=b.w;
        vi[8]=c.x; vi[9]=c.y; vi[10]=c.z; vi[11]=c.w;
    }

    // ---- spin projection ----
    float hr[6], hi[6];
#pragma unroll
    for (int c = 0; c < 3; ++c) {
        if (FWD) { // Pm = 1 - gamma_mu
            if (MU == 0) {
                hr[c]   = vr[c]   + vi[9+c]; hi[c]   = vi[c]   - vr[9+c];
                hr[3+c] = vr[3+c] + vi[6+c]; hi[3+c] = vi[3+c] - vr[6+c];
            } else if (MU == 1) {
                hr[c]   = vr[c]   + vr[9+c]; hi[c]   = vi[c]   + vi[9+c];
                hr[3+c] = vr[3+c] - vr[6+c]; hi[3+c] = vi[3+c] - vi[6+c];
            } else if (MU == 2) {
                hr[c]   = vr[c]   + vi[6+c]; hi[c]   = vi[c]   - vr[6+c];
                hr[3+c] = vr[3+c] - vi[9+c]; hi[3+c] = vi[3+c] + vr[9+c];
            } else {
                hr[c]   = vr[c]   - vr[6+c]; hi[c]   = vi[c]   - vi[6+c];
                hr[3+c] = vr[3+c] - vr[9+c]; hi[3+c] = vi[3+c] - vi[9+c];
            }
        } else { // Pp = 1 + gamma_mu
            if (MU == 0) {
                hr[c]   = vr[c]   - vi[9+c]; hi[c]   = vi[c]   + vr[9+c];
                hr[3+c] = vr[3+c] - vi[6+c]; hi[3+c] = vi[3+c] + vr[6+c];
            } else if (MU == 1) {
                hr[c]   = vr[c]   - vr[9+c]; hi[c]   = vi[c]   - vi[9+c];
                hr[3+c] = vr[3+c] + vr[6+c]; hi[3+c] = vi[3+c] + vi[6+c];
            } else if (MU == 2) {
                hr[c]   = vr[c]   - vi[6+c]; hi[c]   = vi[c]   + vr[6+c];
                hr[3+c] = vr[3+c] + vi[9+c]; hi[3+c] = vi[3+c] - vr[9+c];
            } else {
                hr[c]   = vr[c]   + vr[6+c]; hi[c]   = vi[c]   + vi[6+c];
                hr[3+c] = vr[3+c] + vr[9+c]; hi[3+c] = vi[3+c] + vi[9+c];
            }
        }
    }

    // ---- color multiply: a = U h (fwd) or U^dag h (bwd), const-indexed ----
    float ar[6] = {0,0,0,0,0,0}, ai[6] = {0,0,0,0,0,0};
#pragma unroll
    for (int i = 0; i < 3; ++i) {
#pragma unroll
        for (int j = 0; j < 3; ++j) {
            float urr = FWD ? u_r[i*3 + j] :  u_r[j*3 + i];
            float uii = FWD ? u_i[i*3 + j] : -u_i[j*3 + i];
            ar[i]   += urr*hr[j]   - uii*hi[j];
            ai[i]   += urr*hi[j]   + uii*hr[j];
            ar[3+i] += urr*hr[3+j] - uii*hi[3+j];
            ai[3+i] += urr*hi[3+j] + uii*hr[3+j];
        }
    }

    // ---- reconstruct ----
#pragma unroll
    for (int c = 0; c < 3; ++c) {
        rr[c]   += ar[c];   ri[c]   += ai[c];
        rr[3+c] += ar[3+c]; ri[3+c] += ai[3+c];
        if (FWD) {
            if (MU == 0) {
                rr[6+c] -= ai[3+c]; ri[6+c] += ar[3+c];
                rr[9+c] -= ai[c];   ri[9+c] += ar[c];
            } else if (MU == 1) {
                rr[6+c] -= ar[3+c]; ri[6+c] -= ai[3+c];
                rr[9+c] += ar[c];   ri[9+c] += ai[c];
            } else if (MU == 2) {
                rr[6+c] -= ai[c];   ri[6+c] += ar[c];
                rr[9+c] += ai[3+c]; ri[9+c] -= ar[3+c];
            } else {
                rr[6+c] -= ar[c];   ri[6+c] -= ai[c];
                rr[9+c] -= ar[3+c]; ri[9+c] -= ai[3+c];
            }
        } else {
            if (MU == 0) {
                rr[6+c] += ai[3+c]; ri[6+c] -= ar[3+c];
                rr[9+c] += ai[c];   ri[9+c] -= ar[c];
            } else if (MU == 1) {
                rr[6+c] += ar[3+c]; ri[6+c] += ai[3+c];
                rr[9+c] -= ar[c];   ri[9+c] -= ai[c];
            } else if (MU == 2) {
                rr[6+c] += ai[c];   ri[6+c] -= ar[c];
                rr[9+c] -= ai[3+c]; ri[9+c] += ar[3+c];
            } else {
                rr[6+c] += ar[c];   ri[6+c] += ai[c];
                rr[9+c] += ar[3+c]; ri[9+c] += ai[3+c];
            }
        }
    }
}

// Vector-load the 9-float U slice for direction MU at site s (base float index
// s*36 + MU*9) using only aligned float4/float2/float requests.
template<int MU>
__device__ __forceinline__ void load_slice(const float* __restrict__ U, int s, float u[9])
{
    const float* p = U + (size_t)s * 36;   // 144B block, 16B aligned
    if (MU == 0) {          // floats 0..8
        float4 a = __ldg(reinterpret_cast<const float4*>(p));      // 0..3
        float4 b = __ldg(reinterpret_cast<const float4*>(p) + 1);  // 4..7
        float  c = __ldg(p + 8);
        u[0]=a.x; u[1]=a.y; u[2]=a.z; u[3]=a.w;
        u[4]=b.x; u[5]=b.y; u[6]=b.z; u[7]=b.w; u[8]=c;
    } else if (MU == 1) {   // floats 9..17
        float4 a = __ldg(reinterpret_cast<const float4*>(p + 8));   // 8..11
        float4 b = __ldg(reinterpret_cast<const float4*>(p + 12));  // 12..15
        float2 c = __ldg(reinterpret_cast<const float2*>(p + 16));  // 16,17
        u[0]=a.y; u[1]=a.z; u[2]=a.w;
        u[3]=b.x; u[4]=b.y; u[5]=b.z; u[6]=b.w;
        u[7]=c.x; u[8]=c.y;
    } else if (MU == 2) {   // floats 18..26
        float4 a = __ldg(reinterpret_cast<const float4*>(p + 16));  // 16..19
        float4 b = __ldg(reinterpret_cast<const float4*>(p + 20));  // 20..23
        float4 c = __ldg(reinterpret_cast<const float4*>(p + 24));  // 24..27
        u[0]=a.z; u[1]=a.w;
        u[2]=b.x; u[3]=b.y; u[4]=b.z; u[5]=b.w;
        u[6]=c.x; u[7]=c.y; u[8]=c.z;
    } else {                // floats 27..35
        float  a = __ldg(p + 27);
        float4 b = __ldg(reinterpret_cast<const float4*>(p + 28));  // 28..31
        float4 c = __ldg(reinterpret_cast<const float4*>(p + 32));  // 32..35
        u[0]=a;
        u[1]=b.x; u[2]=b.y; u[3]=b.z; u[4]=b.w;
        u[5]=c.x; u[6]=c.y; u[7]=c.z; u[8]=c.w;
    }
}

__global__ void __launch_bounds__(256, 3)
dslash_kernel(const float* __restrict__ psi_re, const float* __restrict__ psi_im,
              const float* __restrict__ U_re,  const float* __restrict__ U_im,
              float* __restrict__ out_re, float* __restrict__ out_im)
{
    // mu=2 / mu=3 U slices, transposed [element][site] for conflict-free STS/LDS
    __shared__ float s2r[9][256], s2i[9][256], s3r[9][256], s3i[9][256];

    int tid  = threadIdx.x;
    int base = blockIdx.x * 256;
    int site = base + tid;

    int x3 =  site        & 31;
    int x2 = (site >> 5)  & 31;
    int x1 = (site >> 10) & 31;
    int x0 = (site >> 15) & 31;

    const int S0 = 32768, S1 = 1024, S2 = 32, S3 = 1;

    int fw0 = (x0 < 31) ? site + S0 : site - 31*S0;
    int bw0 = (x0 > 0)  ? site - S0 : site + 31*S0;
    int fw1 = (x1 < 31) ? site + S1 : site - 31*S1;
    int bw1 = (x1 > 0)  ? site - S1 : site + 31*S1;
    int fw2 = (x2 < 31) ? site + S2 : site - 31*S2;
    int bw2 = (x2 > 0)  ? site - S2 : site + 31*S2;
    int fw3 = (x3 < 31) ? site + S3 : site - 31*S3;
    int bw3 = (x3 > 0)  ? site - S3 : site + 31*S3;

    // ---- own-site U: 36 floats re + 36 im, vectorized LDG.128 ----
    float ur[36], ui[36];
    {
        const float4* r4 = reinterpret_cast<const float4*>(U_re + (size_t)site * 36);
        const float4* i4 = reinterpret_cast<const float4*>(U_im + (size_t)site * 36);
#pragma unroll
        for (int k = 0; k < 9; ++k) {
            reinterpret_cast<float4*>(ur)[k] = __ldg(r4 + k);
            reinterpret_cast<float4*>(ui)[k] = __ldg(i4 + k);
        }
    }

    // ---- publish mu=2 / mu=3 slices for in-block backward neighbors ----
#pragma unroll
    for (int j = 0; j < 9; ++j) {
        s2r[j][tid] = ur[18 + j];
        s2i[j][tid] = ui[18 + j];
        s3r[j][tid] = ur[27 + j];
        s3i[j][tid] = ui[27 + j];
    }

    float rr[12], ri[12];
#pragma unroll
    for (int k = 0; k < 12; ++k) { rr[k] = 0.f; ri[k] = 0.f; }

    // ---- forward hops: own-site U from registers ----
    hop<0,1>(fw0, psi_re, psi_im, ur +  0, ui +  0, rr, ri);
    hop<1,1>(fw1, psi_re, psi_im, ur +  9, ui +  9, rr, ri);
    hop<2,1>(fw2, psi_re, psi_im, ur + 18, ui + 18, rr, ri);
    hop<3,1>(fw3, psi_re, psi_im, ur + 27, ui + 27, rr, ri);

    __syncthreads();   // slices visible

    // ---- backward mu=3: always in-block (block holds full x3 rows) ----
    {
        int ntid = (tid & 31) ? tid - 1 : tid + 31;
        float br[9], bi[9];
#pragma unroll
        for (int j = 0; j < 9; ++j) { br[j] = s3r[j][ntid]; bi[j] = s3i[j][ntid]; }
        hop<3,0>(bw3, psi_re, psi_im, br, bi, rr, ri);
    }

    // ---- backward mu=2: in-block unless local x2 == 0 ----
    {
        float br[9], bi[9];
        if ((tid >> 5) != 0) {
            int ntid = tid - 32;
#pragma unroll
            for (int j = 0; j < 9; ++j) { br[j] = s2r[j][ntid]; bi[j] = s2i[j][ntid]; }
        } else {
            load_slice<2>(U_re, bw2, br);
            load_slice<2>(U_im, bw2, bi);
        }
        hop<2,0>(bw2, psi_re, psi_im, br, bi, rr, ri);
    }

    // ---- backward mu=1: vectorized global slice ----
    {
        float br[9], bi[9];
        load_slice<1>(U_re, bw1, br);
        load_slice<1>(U_im, bw1, bi);
        hop<1,0>(bw1, psi_re, psi_im, br, bi, rr, ri);
    }

    // ---- backward mu=0: vectorized global slice ----
    {
        float br[9], bi[9];
        load_slice<0>(U_re, bw0, br);
        load_slice<0>(U_im, bw0, bi);
        hop<0,0>(bw0, psi_re, psi_im, br, bi, rr, ri);
    }

    // ---- store: res = -0.5 * accum ----
    float4* o4r = reinterpret_cast<float4*>(out_re + (size_t)site * 12);
    float4* o4i = reinterpret_cast<float4*>(out_im + (size_t)site * 12);
    float4 t;
    t.x = -0.5f*rr[0]; t.y = -0.5f*rr[1]; t.z = -0.5f*rr[2];  t.w = -0.5f*rr[3];  o4r[0] = t;
    t.x = -0.5f*rr[4]; t.y = -0.5f*rr[5]; t.z = -0.5f*rr[6];  t.w = -0.5f*rr[7];  o4r[1] = t;
    t.x = -0.5f*rr[8]; t.y = -0.5f*rr[9]; t.z = -0.5f*rr[10]; t.w = -0.5f*rr[11]; o4r[2] = t;
    t.x = -0.5f*ri[0]; t.y = -0.5f*ri[1]; t.z = -0.5f*ri[2];  t.w = -0.5f*ri[3];  o4i[0] = t;
    t.x = -0.5f*ri[4]; t.y = -0.5f*ri[5]; t.z = -0.5f*ri[6];  t.w = -0.5f*ri[7];  o4i[1] = t;
    t.x = -0.5f*ri[8]; t.y = -0.5f*ri[9]; t.z = -0.5f*ri[10]; t.w = -0.5f*ri[11]; o4i[2] = t;
}

extern "C" void kernel_launch(void* const* d_in, const int* in_sizes, int n_in,
                              void* d_out, int out_size)
{
    const float* psi_re = (const float*)d_in[0];
    const float* psi_im = (const float*)d_in[1];
    const float* U_re   = (const float*)d_in[2];
    const float* U_im   = (const float*)d_in[3];
    // d_in[4..7] are the fixed DeGrand-Rossi projectors; algebra is hardcoded.

    float* out_re = (float*)d_out;
    float* out_im = out_re + (size_t)VOL * 12;

    dslash_kernel<<<VOL / 256, 256>>>(psi_re, psi_im, U_re, U_im, out_re, out_im);
}

// round 7
// speedup vs baseline: 2.0620x; 1.0111x over previous
#include <cuda_runtime.h>

#define VOL (1<<20)   // 32^4

// Wilson Dslash, DeGrand-Rossi basis, spin-projection form.
// psi: [V][4][3] re/im separate. U: [V][4][3][3] re/im separate.
// out: res_re at [0, V*12), res_im at [V*12, 2*V*12).
//
// Block = 256 consecutive sites = 8 full x3-rows.
//  - psi staged in smem: mu=3 hops fully in-block, mu=2 hops in-block for
//    warps 1..6 (local x2 == warp id) -> conflict-free LDS
//  - U read per-slice with aligned vector loads (3 req / 9-float slice)
//  - mu=3 backward U slice shared through smem

template<int MU, int FWD>
__device__ __forceinline__ void hop_core(const float vr[12], const float vi[12],
                                         const float* u_r, const float* u_i,
                                         float rr[12], float ri[12])
{
    // ---- spin projection ----
    float hr[6], hi[6];
#pragma unroll
    for (int c = 0; c < 3; ++c) {
        if (FWD) { // Pm = 1 - gamma_mu
            if (MU == 0) {
                hr[c]   = vr[c]   + vi[9+c]; hi[c]   = vi[c]   - vr[9+c];
                hr[3+c] = vr[3+c] + vi[6+c]; hi[3+c] = vi[3+c] - vr[6+c];
            } else if (MU == 1) {
                hr[c]   = vr[c]   + vr[9+c]; hi[c]   = vi[c]   + vi[9+c];
                hr[3+c] = vr[3+c] - vr[6+c]; hi[3+c] = vi[3+c] - vi[6+c];
            } else if (MU == 2) {
                hr[c]   = vr[c]   + vi[6+c]; hi[c]   = vi[c]   - vr[6+c];
                hr[3+c] = vr[3+c] - vi[9+c]; hi[3+c] = vi[3+c] + vr[9+c];
            } else {
                hr[c]   = vr[c]   - vr[6+c]; hi[c]   = vi[c]   - vi[6+c];
                hr[3+c] = vr[3+c] - vr[9+c]; hi[3+c] = vi[3+c] - vi[9+c];
            }
        } else { // Pp = 1 + gamma_mu
            if (MU == 0) {
                hr[c]   = vr[c]   - vi[9+c]; hi[c]   = vi[c]   + vr[9+c];
                hr[3+c] = vr[3+c] - vi[6+c]; hi[3+c] = vi[3+c] + vr[6+c];
            } else if (MU == 1) {
                hr[c]   = vr[c]   - vr[9+c]; hi[c]   = vi[c]   - vi[9+c];
                hr[3+c] = vr[3+c] + vr[6+c]; hi[3+c] = vi[3+c] + vi[6+c];
            } else if (MU == 2) {
                hr[c]   = vr[c]   - vi[6+c]; hi[c]   = vi[c]   + vr[6+c];
                hr[3+c] = vr[3+c] + vi[9+c]; hi[3+c] = vi[3+c] - vr[9+c];
            } else {
                hr[c]   = vr[c]   + vr[6+c]; hi[c]   = vi[c]   + vi[6+c];
                hr[3+c] = vr[3+c] + vr[9+c]; hi[3+c] = vi[3+c] + vi[9+c];
            }
        }
    }

    // ---- color multiply: a = U h (fwd) or U^dag h (bwd) ----
    float ar[6] = {0,0,0,0,0,0}, ai[6] = {0,0,0,0,0,0};
#pragma unroll
    for (int i = 0; i < 3; ++i) {
#pragma unroll
        for (int j = 0; j < 3; ++j) {
            float urr = FWD ? u_r[i*3 + j] :  u_r[j*3 + i];
            float uii = FWD ? u_i[i*3 + j] : -u_i[j*3 + i];
            ar[i]   += urr*hr[j]   - uii*hi[j];
            ai[i]   += urr*hi[j]   + uii*hr[j];
            ar[3+i] += urr*hr[3+j] - uii*hi[3+j];
            ai[3+i] += urr*hi[3+j] + uii*hr[3+j];
        }
    }

    // ---- reconstruct ----
#pragma unroll
    for (int c = 0; c < 3; ++c) {
        rr[c]   += ar[c];   ri[c]   += ai[c];
        rr[3+c] += ar[3+c]; ri[3+c] += ai[3+c];
        if (FWD) {
            if (MU == 0) {
                rr[6+c] -= ai[3+c]; ri[6+c] += ar[3+c];
                rr[9+c] -= ai[c];   ri[9+c] += ar[c];
            } else if (MU == 1) {
                rr[6+c] -= ar[3+c]; ri[6+c] -= ai[3+c];
                rr[9+c] += ar[c];   ri[9+c] += ai[c];
            } else if (MU == 2) {
                rr[6+c] -= ai[c];   ri[6+c] += ar[c];
                rr[9+c] += ai[3+c]; ri[9+c] -= ar[3+c];
            } else {
                rr[6+c] -= ar[c];   ri[6+c] -= ai[c];
                rr[9+c] -= ar[3+c]; ri[9+c] -= ai[3+c];
            }
        } else {
            if (MU == 0) {
                rr[6+c] += ai[3+c]; ri[6+c] -= ar[3+c];
                rr[9+c] += ai[c];   ri[9+c] -= ar[c];
            } else if (MU == 1) {
                rr[6+c] += ar[3+c]; ri[6+c] += ai[3+c];
                rr[9+c] -= ar[c];   ri[9+c] -= ai[c];
            } else if (MU == 2) {
                rr[6+c] += ai[c];   ri[6+c] -= ar[c];
                rr[9+c] -= ai[3+c]; ri[9+c] += ar[3+c];
            } else {
                rr[6+c] += ar[c];   ri[6+c] += ai[c];
                rr[9+c] += ar[3+c]; ri[9+c] += ai[3+c];
            }
        }
    }
}

__device__ __forceinline__ void load_psi_global(int nbr,
                                                const float* __restrict__ pr,
                                                const float* __restrict__ pi,
                                                float vr[12], float vi[12])
{
    const float4* p4 = reinterpret_cast<const float4*>(pr + (size_t)nbr * 12);
    float4 a = __ldg(p4 + 0), b = __ldg(p4 + 1), c = __ldg(p4 + 2);
    vr[0]=a.x; vr[1]=a.y; vr[2]=a.z; vr[3]=a.w;
    vr[4]=b.x; vr[5]=b.y; vr[6]=b.z; vr[7]=b.w;
    vr[8]=c.x; vr[9]=c.y; vr[10]=c.z; vr[11]=c.w;
    const float4* q4 = reinterpret_cast<const float4*>(pi + (size_t)nbr * 12);
    a = __ldg(q4 + 0); b = __ldg(q4 + 1); c = __ldg(q4 + 2);
    vi[0]=a.x; vi[1]=a.y; vi[2]=a.z; vi[3]=a.w;
    vi[4]=b.x; vi[5]=b.y; vi[6]=b.z; vi[7]=b.w;
    vi[8]=c.x; vi[9]=c.y; vi[10]=c.z; vi[11]=c.w;
}

// Vector-load the 9-float U slice for direction MU at site s (base float index
// s*36 + MU*9) using only aligned float4/float2/float requests.
template<int MU>
__device__ __forceinline__ void load_slice(const float* __restrict__ U, int s, float u[9])
{
    const float* p = U + (size_t)s * 36;   // 144B block, 16B aligned
    if (MU == 0) {
        float4 a = __ldg(reinterpret_cast<const float4*>(p));
        float4 b = __ldg(reinterpret_cast<const float4*>(p) + 1);
        float  c = __ldg(p + 8);
        u[0]=a.x; u[1]=a.y; u[2]=a.z; u[3]=a.w;
        u[4]=b.x; u[5]=b.y; u[6]=b.z; u[7]=b.w; u[8]=c;
    } else if (MU == 1) {
        float4 a = __ldg(reinterpret_cast<const float4*>(p + 8));
        float4 b = __ldg(reinterpret_cast<const float4*>(p + 12));
        float2 c = __ldg(reinterpret_cast<const float2*>(p + 16));
        u[0]=a.y; u[1]=a.z; u[2]=a.w;
        u[3]=b.x; u[4]=b.y; u[5]=b.z; u[6]=b.w;
        u[7]=c.x; u[8]=c.y;
    } else if (MU == 2) {
        float4 a = __ldg(reinterpret_cast<const float4*>(p + 16));
        float4 b = __ldg(reinterpret_cast<const float4*>(p + 20));
        float4 c = __ldg(reinterpret_cast<const float4*>(p + 24));
        u[0]=a.z; u[1]=a.w;
        u[2]=b.x; u[3]=b.y; u[4]=b.z; u[5]=b.w;
        u[6]=c.x; u[7]=c.y; u[8]=c.z;
    } else {
        float  a = __ldg(p + 27);
        float4 b = __ldg(reinterpret_cast<const float4*>(p + 28));
        float4 c = __ldg(reinterpret_cast<const float4*>(p + 32));
        u[0]=a;
        u[1]=b.x; u[2]=b.y; u[3]=b.z; u[4]=b.w;
        u[5]=c.x; u[6]=c.y; u[7]=c.z; u[8]=c.w;
    }
}

__global__ void __launch_bounds__(256, 3)
dslash_kernel(const float* __restrict__ psi_re, const float* __restrict__ psi_im,
              const float* __restrict__ U_re,  const float* __restrict__ U_im,
              float* __restrict__ out_re, float* __restrict__ out_im)
{
    // psi of the block's 256 sites, transposed [element][site]
    __shared__ float spr[12][256], spi[12][256];
    // mu=3 U slices for in-block backward neighbors
    __shared__ float s3r[9][256], s3i[9][256];

    int tid  = threadIdx.x;
    int base = blockIdx.x * 256;
    int site = base + tid;

    int x3 =  tid         & 31;   // low 5 bits of site
    int wrp =  tid >> 5;          // local x2 (warp id)
    int x2 = (site >> 5)  & 31;
    int x1 = (site >> 10) & 31;
    int x0 = (site >> 15) & 31;

    const int S0 = 32768, S1 = 1024, S2 = 32;

    int fw0 = (x0 < 31) ? site + S0 : site - 31*S0;
    int bw0 = (x0 > 0)  ? site - S0 : site + 31*S0;
    int fw1 = (x1 < 31) ? site + S1 : site - 31*S1;
    int bw1 = (x1 > 0)  ? site - S1 : site + 31*S1;
    int fw2 = (x2 < 31) ? site + S2 : site - 31*S2;
    int bw2 = (x2 > 0)  ? site - S2 : site + 31*S2;

    // ---- publish own psi + own mu=3 U slice to smem ----
    {
        const float4* p4 = reinterpret_cast<const float4*>(psi_re + (size_t)site * 12);
        const float4* q4 = reinterpret_cast<const float4*>(psi_im + (size_t)site * 12);
#pragma unroll
        for (int k = 0; k < 3; ++k) {
            float4 a = __ldg(p4 + k);
            spr[4*k+0][tid] = a.x; spr[4*k+1][tid] = a.y;
            spr[4*k+2][tid] = a.z; spr[4*k+3][tid] = a.w;
            float4 b = __ldg(q4 + k);
            spi[4*k+0][tid] = b.x; spi[4*k+1][tid] = b.y;
            spi[4*k+2][tid] = b.z; spi[4*k+3][tid] = b.w;
        }
        float u3r[9], u3i[9];
        load_slice<3>(U_re, site, u3r);
        load_slice<3>(U_im, site, u3i);
#pragma unroll
        for (int j = 0; j < 9; ++j) { s3r[j][tid] = u3r[j]; s3i[j][tid] = u3i[j]; }
    }
    __syncthreads();

    float rr[12], ri[12];
#pragma unroll
    for (int k = 0; k < 12; ++k) { rr[k] = 0.f; ri[k] = 0.f; }

    float vr[12], vi[12], uar[9], uai[9];

    // ---- mu=3 forward: psi + U from smem/regs (in-block always) ----
    {
        int nt = (x3 < 31) ? tid + 1 : tid - 31;
#pragma unroll
        for (int k = 0; k < 12; ++k) { vr[k] = spr[k][nt]; vi[k] = spi[k][nt]; }
#pragma unroll
        for (int j = 0; j < 9; ++j) { uar[j] = s3r[j][tid]; uai[j] = s3i[j][tid]; }
        hop_core<3,1>(vr, vi, uar, uai, rr, ri);
    }
    // ---- mu=3 backward: psi + U from smem (in-block always) ----
    {
        int nt = (x3 > 0) ? tid - 1 : tid + 31;
#pragma unroll
        for (int k = 0; k < 12; ++k) { vr[k] = spr[k][nt]; vi[k] = spi[k][nt]; }
#pragma unroll
        for (int j = 0; j < 9; ++j) { uar[j] = s3r[j][nt]; uai[j] = s3i[j][nt]; }
        hop_core<3,0>(vr, vi, uar, uai, rr, ri);
    }

    // ---- mu=2 forward: psi smem for warps 0..6, global for warp 7 ----
    {
        if (wrp < 7) {
            int nt = tid + 32;
#pragma unroll
            for (int k = 0; k < 12; ++k) { vr[k] = spr[k][nt]; vi[k] = spi[k][nt]; }
        } else {
            load_psi_global(fw2, psi_re, psi_im, vr, vi);
        }
        load_slice<2>(U_re, site, uar);
        load_slice<2>(U_im, site, uai);
        hop_core<2,1>(vr, vi, uar, uai, rr, ri);
    }
    // ---- mu=2 backward: psi smem for warps 1..7, global for warp 0 ----
    {
        if (wrp > 0) {
            int nt = tid - 32;
#pragma unroll
            for (int k = 0; k < 12; ++k) { vr[k] = spr[k][nt]; vi[k] = spi[k][nt]; }
        } else {
            load_psi_global(bw2, psi_re, psi_im, vr, vi);
        }
        load_slice<2>(U_re, bw2, uar);   // L1 hit for warps 1..7 (loaded by tid-32)
        load_slice<2>(U_im, bw2, uai);
        hop_core<2,0>(vr, vi, uar, uai, rr, ri);
    }

    // ---- mu=1 forward / backward: global ----
    {
        load_psi_global(fw1, psi_re, psi_im, vr, vi);
        load_slice<1>(U_re, site, uar);
        load_slice<1>(U_im, site, uai);
        hop_core<1,1>(vr, vi, uar, uai, rr, ri);
    }
    {
        load_psi_global(bw1, psi_re, psi_im, vr, vi);
        load_slice<1>(U_re, bw1, uar);
        load_slice<1>(U_im, bw1, uai);
        hop_core<1,0>(vr, vi, uar, uai, rr, ri);
    }

    // ---- mu=0 forward / backward: global ----
    {
        load_psi_global(fw0, psi_re, psi_im, vr, vi);
        load_slice<0>(U_re, site, uar);
        load_slice<0>(U_im, site, uai);
        hop_core<0,1>(vr, vi, uar, uai, rr, ri);
    }
    {
        load_psi_global(bw0, psi_re, psi_im, vr, vi);
        load_slice<0>(U_re, bw0, uar);
        load_slice<0>(U_im, bw0, uai);
        hop_core<0,0>(vr, vi, uar, uai, rr, ri);
    }

    // ---- store: res = -0.5 * accum ----
    float4* o4r = reinterpret_cast<float4*>(out_re + (size_t)site * 12);
    float4* o4i = reinterpret_cast<float4*>(out_im + (size_t)site * 12);
    float4 t;
    t.x = -0.5f*rr[0]; t.y = -0.5f*rr[1]; t.z = -0.5f*rr[2];  t.w = -0.5f*rr[3];  o4r[0] = t;
    t.x = -0.5f*rr[4]; t.y = -0.5f*rr[5]; t.z = -0.5f*rr[6];  t.w = -0.5f*rr[7];  o4r[1] = t;
    t.x = -0.5f*rr[8]; t.y = -0.5f*rr[9]; t.z = -0.5f*rr[10]; t.w = -0.5f*rr[11]; o4r[2] = t;
    t.x = -0.5f*ri[0]; t.y = -0.5f*ri[1]; t.z = -0.5f*ri[2];  t.w = -0.5f*ri[3];  o4i[0] = t;
    t.x = -0.5f*ri[4]; t.y = -0.5f*ri[5]; t.z = -0.5f*ri[6];  t.w = -0.5f*ri[7];  o4i[1] = t;
    t.x = -0.5f*ri[8]; t.y = -0.5f*ri[9]; t.z = -0.5f*ri[10]; t.w = -0.5f*ri[11]; o4i[2] = t;
}

extern "C" void kernel_launch(void* const* d_in, const int* in_sizes, int n_in,
                              void* d_out, int out_size)
{
    const float* psi_re = (const float*)d_in[0];
    const float* psi_im = (const float*)d_in[1];
    const float* U_re   = (const float*)d_in[2];
    const float* U_im   = (const float*)d_in[3];
    // d_in[4..7] are the fixed DeGrand-Rossi projectors; algebra is hardcoded.

    float* out_re = (float*)d_out;
    float* out_im = out_re + (size_t)VOL * 12;

    dslash_kernel<<<VOL / 256, 256>>>(psi_re, psi_im, U_re, U_im, out_re, out_im);
}